// round 12
// baseline (speedup 1.0000x reference)
#include <cuda_runtime.h>
#include <cuda_fp16.h>

#define N_GOAL 16384
#define N_OBS  65536
#define N_TASK 8192
#define NE1    1048576
#define NE2    1048576
#define FDIM   128
#define SDIM   64
#define CAP1   64
#define CAP2   256

typedef unsigned long long ull;

// Scratch (static device globals — no runtime allocation)
__device__ __half g_pgh[N_GOAL * SDIM];  // x_goal @ W1 in fp16  (2 MB)
__device__ float  g_buf1[N_OBS * SDIM];  // x_obs@W1 -> h        (16 MB)
__device__ __half g_x1h[N_OBS * SDIM];   // x1 activations fp16  (8 MB)
__device__ float  g_buf2[N_TASK * SDIM]; // x_task + agg2        (2 MB)
__device__ int    g_cnt1[N_OBS];
__device__ int    g_cnt2[N_TASK];
__device__ int    g_bkt1[N_OBS * CAP1];  // (16 MB)
__device__ int    g_bkt2[N_TASK * CAP2]; // (8 MB)

// Packed f32x2 FMA (Blackwell): d = a*b + c lane-wise on two packed floats.
__device__ __forceinline__ ull ffma2(ull a, ull b, ull c) {
    ull d;
    asm("fma.rn.f32x2 %0, %1, %2, %3;" : "=l"(d) : "l"(a), "l"(b), "l"(c));
    return d;
}
__device__ __forceinline__ float2 unpack2(ull v) {
    float2 f;
    asm("mov.b64 {%0, %1}, %2;" : "=f"(f.x), "=f"(f.y) : "l"(v));
    return f;
}
// Accumulate 8 fp16 values (one uint4) into 8 fp32 accumulators.
__device__ __forceinline__ void acc_h8(float* a, uint4 v) {
    float2 f0 = __half22float2(*(const __half2*)&v.x);
    float2 f1 = __half22float2(*(const __half2*)&v.y);
    float2 f2 = __half22float2(*(const __half2*)&v.z);
    float2 f3 = __half22float2(*(const __half2*)&v.w);
    a[0] += f0.x; a[1] += f0.y; a[2] += f1.x; a[3] += f1.y;
    a[4] += f2.x; a[5] += f2.y; a[6] += f3.x; a[7] += f3.y;
}

// ---------------------------------------------------------------------------
__global__ void zero_counts() {
    int i = blockIdx.x * blockDim.x + threadIdx.x;
    if (i < N_OBS) g_cnt1[i] = 0;
    if (i < N_TASK) g_cnt2[i] = 0;
}

// One pass over both edge sets; one 4B atomic per edge. (R10 proven)
__global__ void build_all(const int* __restrict__ s1, const int* __restrict__ d1,
                          const int* __restrict__ s2, const int* __restrict__ d2) {
    int e = blockIdx.x * blockDim.x + threadIdx.x;
    if (e < NE1) {
        int s = s1[e], d = d1[e];
        int slot = atomicAdd(&g_cnt1[d], 1);
        if (slot < CAP1) g_bkt1[d * CAP1 + slot] = s;
    } else {
        int e2 = e - NE1;
        int s = s2[e2], d = d2[e2];
        int slot = atomicAdd(&g_cnt2[d], 1);
        if (slot < CAP2) g_bkt2[d * CAP2 + slot] = s;
    }
}

// ---------------------------------------------------------------------------
// projAll (R10 proven): rows 0..N_GOAL-1 -> g_pgh (fp16), rest -> g_buf1.
#define XP 132
__global__ __launch_bounds__(256) void projAll(const float* __restrict__ xg,
                                               const float* __restrict__ xo,
                                               const float* __restrict__ W) {
    extern __shared__ float sm[];
    float* Xs = sm;                 // 64 rows x XP   (33792 B)
    float* Wt = sm + 64 * XP;       // Wt[c][k], 64 x XP (33792 B)
    int t = threadIdx.x;

    for (int i = t; i < FDIM * SDIM; i += 256) {
        int k = i >> 6, c = i & 63;
        Wt[c * XP + k] = W[i];
    }

    const float* X; int rowbase; bool is_goal;
    if (blockIdx.x < N_GOAL / 64) {
        X = xg; rowbase = blockIdx.x * 64; is_goal = true;
    } else {
        X = xo; rowbase = (blockIdx.x - N_GOAL / 64) * 64; is_goal = false;
    }

    const float4* X4 = (const float4*)(X + (size_t)rowbase * FDIM);
    for (int i = t; i < 64 * 32; i += 256) {
        int row = i >> 5, kq = i & 31;
        *(float4*)&Xs[row * XP + kq * 4] = X4[row * 32 + kq];
    }
    __syncthreads();

    int warp = t >> 5, lane = t & 31;
    ull acc0[8], acc1[8];
#pragma unroll
    for (int i = 0; i < 8; i++) { acc0[i] = 0ull; acc1[i] = 0ull; }

    const float* xb = Xs + warp * 8 * XP;
#pragma unroll 4
    for (int k = 0; k < FDIM; k += 4) {
        ulonglong2 wA = *(const ulonglong2*)&Wt[lane * XP + k];
        ulonglong2 wB = *(const ulonglong2*)&Wt[(lane + 32) * XP + k];
#pragma unroll
        for (int i = 0; i < 8; i++) {
            ulonglong2 xh = *(const ulonglong2*)&xb[i * XP + k];
            acc0[i] = ffma2(xh.x, wA.x, acc0[i]);
            acc0[i] = ffma2(xh.y, wA.y, acc0[i]);
            acc1[i] = ffma2(xh.x, wB.x, acc1[i]);
            acc1[i] = ffma2(xh.y, wB.y, acc1[i]);
        }
    }
    int row0 = rowbase + warp * 8;
#pragma unroll
    for (int i = 0; i < 8; i++) {
        float2 fa = unpack2(acc0[i]);
        float2 fb = unpack2(acc1[i]);
        float va = fa.x + fa.y, vb = fb.x + fb.y;
        if (is_goal) {
            g_pgh[(size_t)(row0 + i) * SDIM + lane]      = __float2half(va);
            g_pgh[(size_t)(row0 + i) * SDIM + lane + 32] = __float2half(vb);
        } else {
            g_buf1[(size_t)(row0 + i) * SDIM + lane]      = va;
            g_buf1[(size_t)(row0 + i) * SDIM + lane + 32] = vb;
        }
    }
}

// ---------------------------------------------------------------------------
// gather1_split: edge-parallel agg1 (mirror of gather2_split).
// Block = 8 obs rows x 32 thr/row: h in 0..3 = edge subset, q = 16B chunk.
// In-place: g_buf1[d] = relu(g_buf1[d] + sum pg[s] + b1).
__global__ __launch_bounds__(256) void gather1_split(const float* __restrict__ b1) {
    int t = threadIdx.x;
    int r = t >> 5;           // 0..7 (warp = one row)
    int h = (t >> 3) & 3;     // edge subset
    int q = t & 7;            // chunk -> cols [8q, 8q+8)
    int d = blockIdx.x * 8 + r;
    int n = g_cnt1[d]; if (n > CAP1) n = CAP1;
    const uint4* pgh = (const uint4*)g_pgh;
    float a[8];
#pragma unroll
    for (int i = 0; i < 8; i++) a[i] = 0.f;
    const int* bkt = g_bkt1 + d * CAP1;

    for (int j = h * 4; j + 4 <= n; j += 16) {
        int4 s4 = *(const int4*)(bkt + j);
        uint4 v0 = pgh[s4.x * 8 + q];
        uint4 v1 = pgh[s4.y * 8 + q];
        uint4 v2 = pgh[s4.z * 8 + q];
        uint4 v3 = pgh[s4.w * 8 + q];
        acc_h8(a, v0); acc_h8(a, v1); acc_h8(a, v2); acc_h8(a, v3);
    }
    if (h == ((n >> 2) & 3)) {           // remainder edges (n % 4)
        for (int jj = n & ~3; jj < n; jj++) acc_h8(a, pgh[bkt[jj] * 8 + q]);
    }
    // combine 4 edge-subsets: butterfly over lane bits 3,4 (h)
#pragma unroll
    for (int i = 0; i < 8; i++) {
        a[i] += __shfl_xor_sync(0xffffffffu, a[i], 8);
        a[i] += __shfl_xor_sync(0xffffffffu, a[i], 16);
    }
    if (h == 0) {
        float4 s0 = ((const float4*)g_buf1)[d * 16 + 2 * q];
        float4 s1 = ((const float4*)g_buf1)[d * 16 + 2 * q + 1];
        float4 o0 = make_float4(fmaxf(a[0] + s0.x + b1[8 * q + 0], 0.f),
                                fmaxf(a[1] + s0.y + b1[8 * q + 1], 0.f),
                                fmaxf(a[2] + s0.z + b1[8 * q + 2], 0.f),
                                fmaxf(a[3] + s0.w + b1[8 * q + 3], 0.f));
        float4 o1 = make_float4(fmaxf(a[4] + s1.x + b1[8 * q + 4], 0.f),
                                fmaxf(a[5] + s1.y + b1[8 * q + 5], 0.f),
                                fmaxf(a[6] + s1.z + b1[8 * q + 6], 0.f),
                                fmaxf(a[7] + s1.w + b1[8 * q + 7], 0.f));
        ((float4*)g_buf1)[d * 16 + 2 * q]     = o0;
        ((float4*)g_buf1)[d * 16 + 2 * q + 1] = o1;
    }
}

// ---------------------------------------------------------------------------
// mlp1: x1 = relu(h @ W2 + b2), h = g_buf1 (post bias+ReLU). 32 rows/block.
// GEMM phase identical to the proven g1mlp1 second phase; h staged coalesced.
#define HST 68
__global__ __launch_bounds__(256) void mlp1(const float* __restrict__ W2,
                                            const float* __restrict__ b2) {
    __shared__ float Hs[32 * HST];        // 8704 B
    __shared__ float W2t[SDIM * HST];     // 17408 B, W2t[c][k]
    int t = threadIdx.x;
    for (int i = t; i < SDIM * SDIM; i += 256) {
        int k = i >> 6, c = i & 63;
        W2t[c * HST + k] = W2[i];
    }

    int r = t >> 3, q = t & 7;
    int d = blockIdx.x * 32 + r;
    float4 s0 = ((const float4*)g_buf1)[d * 16 + 2 * q];
    float4 s1 = ((const float4*)g_buf1)[d * 16 + 2 * q + 1];
    *(float4*)&Hs[r * HST + 8 * q]     = s0;
    *(float4*)&Hs[r * HST + 8 * q + 4] = s1;
    __syncthreads();

    // ---- GEMM: warp owns 4 rows; lane owns cols {lane, lane+32} ----
    int warp = t >> 5, lane = t & 31;
    ull acc0[4] = {0ull, 0ull, 0ull, 0ull};
    ull acc1[4] = {0ull, 0ull, 0ull, 0ull};
    const float* hb = Hs + warp * 4 * HST;
#pragma unroll
    for (int k = 0; k < SDIM; k += 4) {
        ulonglong2 wA = *(const ulonglong2*)&W2t[lane * HST + k];
        ulonglong2 wB = *(const ulonglong2*)&W2t[(lane + 32) * HST + k];
#pragma unroll
        for (int i = 0; i < 4; i++) {
            ulonglong2 xh = *(const ulonglong2*)&hb[i * HST + k];
            acc0[i] = ffma2(xh.x, wA.x, acc0[i]);
            acc0[i] = ffma2(xh.y, wA.y, acc0[i]);
            acc1[i] = ffma2(xh.x, wB.x, acc1[i]);
            acc1[i] = ffma2(xh.y, wB.y, acc1[i]);
        }
    }
    int row0 = blockIdx.x * 32 + warp * 4;
    float b2a = b2[lane], b2b = b2[lane + 32];
#pragma unroll
    for (int i = 0; i < 4; i++) {
        float2 fa = unpack2(acc0[i]);
        float2 fb = unpack2(acc1[i]);
        g_x1h[(size_t)(row0 + i) * SDIM + lane] =
            __float2half(fmaxf(fa.x + fa.y + b2a, 0.f));
        g_x1h[(size_t)(row0 + i) * SDIM + lane + 32] =
            __float2half(fmaxf(fb.x + fb.y + b2b, 0.f));
    }
}

// ---------------------------------------------------------------------------
// gather2_split (R10 proven): edge-parallel agg2. Block = 8 rows x 32 thr.
__global__ __launch_bounds__(256) void gather2_split(const float4* __restrict__ x_task) {
    int t = threadIdx.x;
    int r = t >> 5;           // 0..7 (warp = one row)
    int h = (t >> 3) & 3;     // edge subset
    int q = t & 7;            // chunk
    int d = blockIdx.x * 8 + r;
    int n = g_cnt2[d]; if (n > CAP2) n = CAP2;
    const uint4* x1h = (const uint4*)g_x1h;
    float a[8];
#pragma unroll
    for (int i = 0; i < 8; i++) a[i] = 0.f;
    const int* bkt = g_bkt2 + d * CAP2;

    for (int j = h * 4; j + 4 <= n; j += 16) {
        int4 s4 = *(const int4*)(bkt + j);
        uint4 v0 = x1h[s4.x * 8 + q];
        uint4 v1 = x1h[s4.y * 8 + q];
        uint4 v2 = x1h[s4.z * 8 + q];
        uint4 v3 = x1h[s4.w * 8 + q];
        acc_h8(a, v0); acc_h8(a, v1); acc_h8(a, v2); acc_h8(a, v3);
    }
    if (h == ((n >> 2) & 3)) {           // remainder edges (n % 4)
        for (int jj = n & ~3; jj < n; jj++) acc_h8(a, x1h[bkt[jj] * 8 + q]);
    }
#pragma unroll
    for (int i = 0; i < 8; i++) {
        a[i] += __shfl_xor_sync(0xffffffffu, a[i], 8);
        a[i] += __shfl_xor_sync(0xffffffffu, a[i], 16);
    }
    if (h == 0) {
        float4 s0 = x_task[d * 16 + 2 * q];
        float4 s1 = x_task[d * 16 + 2 * q + 1];
        ((float4*)g_buf2)[d * 16 + 2 * q] =
            make_float4(a[0] + s0.x, a[1] + s0.y, a[2] + s0.z, a[3] + s0.w);
        ((float4*)g_buf2)[d * 16 + 2 * q + 1] =
            make_float4(a[4] + s1.x, a[5] + s1.y, a[6] + s1.z, a[7] + s1.w);
    }
}

// ---------------------------------------------------------------------------
// mlp2pool (R10 proven): block = one graph = 32 task rows, 256 threads.
#define XSTR 68
#define WSTR 65
__global__ __launch_bounds__(256) void mlp2pool(const float* __restrict__ W3,
                                                const float* __restrict__ b3,
                                                const float* __restrict__ W4,
                                                const float* __restrict__ b4,
                                                const float* __restrict__ Wc1,
                                                const float* __restrict__ bc1,
                                                const float* __restrict__ Wc2,
                                                const float* __restrict__ bc2,
                                                float* __restrict__ out) {
    __shared__ float Xs[32 * XSTR];
    __shared__ float W3t[SDIM * WSTR];    // transposed [c][k]
    __shared__ float W4s[SDIM], b3s[SDIM];
    __shared__ float scal[32];
    int t = threadIdx.x;
    for (int i = t; i < SDIM * SDIM; i += 256) {
        int k = i >> 6, c = i & 63;
        W3t[c * WSTR + k] = W3[i];
    }
    if (t < SDIM) { W4s[t] = W4[t]; b3s[t] = b3[t]; }

    int r = t >> 3, q = t & 7;
    int d = blockIdx.x * 32 + r;
    float4 a0 = ((const float4*)g_buf2)[d * 16 + 2 * q];
    float4 a1 = ((const float4*)g_buf2)[d * 16 + 2 * q + 1];
    *(float4*)&Xs[r * XSTR + 8 * q]     = a0;
    *(float4*)&Xs[r * XSTR + 8 * q + 4] = a1;
    __syncthreads();

    float s8[8];
    int cbase = q * 8;
#pragma unroll
    for (int i = 0; i < 8; i++) s8[i] = b3s[cbase + i];
    const float* xrow = Xs + r * XSTR;
#pragma unroll 4
    for (int k = 0; k < SDIM; k++) {
        float xv = xrow[k];
#pragma unroll
        for (int i = 0; i < 8; i++)
            s8[i] = fmaf(xv, W3t[(cbase + i) * WSTR + k], s8[i]);
    }
    float partial = 0.f;
#pragma unroll
    for (int i = 0; i < 8; i++)
        partial = fmaf(fmaxf(s8[i], 0.f), W4s[cbase + i], partial);
#pragma unroll
    for (int o = 1; o < 8; o <<= 1)
        partial += __shfl_xor_sync(0xffffffffu, partial, o);
    if (q == 0) scal[r] = partial + b4[0];
    __syncthreads();

    if (t < 32) {
        float v = scal[t];
        float vmax = v, vsum = v;
#pragma unroll
        for (int o = 16; o; o >>= 1) {
            vmax = fmaxf(vmax, __shfl_xor_sync(0xffffffffu, vmax, o));
            vsum += __shfl_xor_sync(0xffffffffu, vsum, o);
        }
        if (t == 0) {
            float mx = vmax;
            float mn = vsum * (1.f / 32.f);
            float rr = bc2[0];
#pragma unroll
            for (int i = 0; i < 8; i++) {
                float h = fmaxf(fmaf(mx, Wc1[i], fmaf(mn, Wc1[8 + i], bc1[i])), 0.f);
                rr = fmaf(h, Wc2[i], rr);
            }
            out[blockIdx.x] = rr;
        }
    }
}

// ---------------------------------------------------------------------------
extern "C" void kernel_launch(void* const* d_in, const int* in_sizes, int n_in,
                              void* d_out, int out_size) {
    const float* x_goal = (const float*)d_in[0];
    const float* x_obs  = (const float*)d_in[1];
    const float* x_task = (const float*)d_in[2];
    const int* ei_go_src = (const int*)d_in[3];
    const int* ei_go_dst = (const int*)d_in[4];
    const int* ei_ot_src = (const int*)d_in[5];
    const int* ei_ot_dst = (const int*)d_in[6];
    // d_in[7] = task_batch (contiguous; unused)
    const float* W1  = (const float*)d_in[8];
    const float* b1  = (const float*)d_in[9];
    const float* W2  = (const float*)d_in[10];
    const float* b2  = (const float*)d_in[11];
    const float* W3  = (const float*)d_in[12];
    const float* b3  = (const float*)d_in[13];
    const float* W4  = (const float*)d_in[14];
    const float* b4  = (const float*)d_in[15];
    const float* Wc1 = (const float*)d_in[16];
    const float* bc1 = (const float*)d_in[17];
    const float* Wc2 = (const float*)d_in[18];
    const float* bc2 = (const float*)d_in[19];
    float* out = (float*)d_out;

    const int PROJ_SMEM = 2 * 64 * XP * sizeof(float);   // 67584 B
    cudaFuncSetAttribute(projAll, cudaFuncAttributeMaxDynamicSharedMemorySize,
                         PROJ_SMEM);

    // 1. zero counters
    zero_counts<<<N_OBS / 256, 256>>>();
    // 2. bucket both edge sets
    build_all<<<(NE1 + NE2) / 256, 256>>>(ei_go_src, ei_go_dst, ei_ot_src, ei_ot_dst);
    // 3. pg(fp16) = x_goal @ W1 ; buf1(fp32) = x_obs @ W1
    projAll<<<(N_GOAL + N_OBS) / 64, 256, PROJ_SMEM>>>(x_goal, x_obs, W1);
    // 4. agg1 edge-parallel, in-place: buf1 = relu(buf1 + agg + b1)
    gather1_split<<<N_OBS / 8, 256>>>(b1);
    // 5. x1(fp16) = relu(buf1 @ W2 + b2)
    mlp1<<<N_OBS / 32, 256>>>(W2, b2);
    // 6. agg2 edge-parallel -> g_buf2 (fp32)
    gather2_split<<<N_TASK / 8, 256>>>((const float4*)x_task);
    // 7. MLP2 + pooling + critic -> out
    mlp2pool<<<N_TASK / 32, 256>>>(W3, b3, W4, b4, Wc1, bc1, Wc2, bc2, out);
}

// round 13
// speedup vs baseline: 1.0496x; 1.0496x over previous
#include <cuda_runtime.h>
#include <cuda_fp16.h>

#define N_GOAL 16384
#define N_OBS  65536
#define N_TASK 8192
#define NE1    1048576
#define NE2    1048576
#define FDIM   128
#define SDIM   64
#define CAP1   64
#define CAP2   256

typedef unsigned long long ull;

// Scratch (static device globals — no runtime allocation)
__device__ __half g_pgh[N_GOAL * SDIM];  // x_goal @ W1 in fp16  (2 MB)
__device__ float  g_buf1[N_OBS * SDIM];  // x_obs  @ W1          (16 MB)
__device__ __half g_x1h[N_OBS * SDIM];   // x1 activations fp16  (8 MB)
__device__ float  g_buf2[N_TASK * SDIM]; // x_task + agg2        (2 MB)
__device__ int    g_cnt1[N_OBS];
__device__ int    g_cnt2[N_TASK];
__device__ int    g_bkt1[N_OBS * CAP1];  // (16 MB)
__device__ int    g_bkt2[N_TASK * CAP2]; // (8 MB)

// Packed f32x2 FMA (Blackwell): d = a*b + c lane-wise on two packed floats.
__device__ __forceinline__ ull ffma2(ull a, ull b, ull c) {
    ull d;
    asm("fma.rn.f32x2 %0, %1, %2, %3;" : "=l"(d) : "l"(a), "l"(b), "l"(c));
    return d;
}
__device__ __forceinline__ float2 unpack2(ull v) {
    float2 f;
    asm("mov.b64 {%0, %1}, %2;" : "=f"(f.x), "=f"(f.y) : "l"(v));
    return f;
}
// Accumulate 8 fp16 values (one uint4) into 8 fp32 accumulators.
__device__ __forceinline__ void acc_h8(float* a, uint4 v) {
    float2 f0 = __half22float2(*(const __half2*)&v.x);
    float2 f1 = __half22float2(*(const __half2*)&v.y);
    float2 f2 = __half22float2(*(const __half2*)&v.z);
    float2 f3 = __half22float2(*(const __half2*)&v.w);
    a[0] += f0.x; a[1] += f0.y; a[2] += f1.x; a[3] += f1.y;
    a[4] += f2.x; a[5] += f2.y; a[6] += f3.x; a[7] += f3.y;
}

// ---------------------------------------------------------------------------
// One pass over both edge sets; one 4B atomic per edge.
__global__ void build_all(const int* __restrict__ s1, const int* __restrict__ d1,
                          const int* __restrict__ s2, const int* __restrict__ d2) {
    int e = blockIdx.x * blockDim.x + threadIdx.x;
    if (e < NE1) {
        int s = s1[e], d = d1[e];
        int slot = atomicAdd(&g_cnt1[d], 1);
        if (slot < CAP1) g_bkt1[d * CAP1 + slot] = s;
    } else {
        int e2 = e - NE1;
        int s = s2[e2], d = d2[e2];
        int slot = atomicAdd(&g_cnt2[d], 1);
        if (slot < CAP2) g_bkt2[d * CAP2 + slot] = s;
    }
}

// ---------------------------------------------------------------------------
// projAll: rows 0..N_GOAL-1 -> g_pgh (fp16), rest -> g_buf1 (fp32).
// f32x2 packed-along-K; X and W staged in smem.
#define XP 132
__global__ __launch_bounds__(256) void projAll(const float* __restrict__ xg,
                                               const float* __restrict__ xo,
                                               const float* __restrict__ W) {
    extern __shared__ float sm[];
    float* Xs = sm;                 // 64 rows x XP   (33792 B)
    float* Wt = sm + 64 * XP;       // Wt[c][k], 64 x XP (33792 B)
    int t = threadIdx.x;

    for (int i = t; i < FDIM * SDIM; i += 256) {
        int k = i >> 6, c = i & 63;
        Wt[c * XP + k] = W[i];
    }

    const float* X; int rowbase; bool is_goal;
    if (blockIdx.x < N_GOAL / 64) {
        X = xg; rowbase = blockIdx.x * 64; is_goal = true;
    } else {
        X = xo; rowbase = (blockIdx.x - N_GOAL / 64) * 64; is_goal = false;
    }

    const float4* X4 = (const float4*)(X + (size_t)rowbase * FDIM);
    for (int i = t; i < 64 * 32; i += 256) {
        int row = i >> 5, kq = i & 31;
        *(float4*)&Xs[row * XP + kq * 4] = X4[row * 32 + kq];
    }
    __syncthreads();

    int warp = t >> 5, lane = t & 31;
    ull acc0[8], acc1[8];
#pragma unroll
    for (int i = 0; i < 8; i++) { acc0[i] = 0ull; acc1[i] = 0ull; }

    const float* xb = Xs + warp * 8 * XP;
#pragma unroll 4
    for (int k = 0; k < FDIM; k += 4) {
        ulonglong2 wA = *(const ulonglong2*)&Wt[lane * XP + k];
        ulonglong2 wB = *(const ulonglong2*)&Wt[(lane + 32) * XP + k];
#pragma unroll
        for (int i = 0; i < 8; i++) {
            ulonglong2 xh = *(const ulonglong2*)&xb[i * XP + k];
            acc0[i] = ffma2(xh.x, wA.x, acc0[i]);
            acc0[i] = ffma2(xh.y, wA.y, acc0[i]);
            acc1[i] = ffma2(xh.x, wB.x, acc1[i]);
            acc1[i] = ffma2(xh.y, wB.y, acc1[i]);
        }
    }
    int row0 = rowbase + warp * 8;
#pragma unroll
    for (int i = 0; i < 8; i++) {
        float2 fa = unpack2(acc0[i]);
        float2 fb = unpack2(acc1[i]);
        float va = fa.x + fa.y, vb = fb.x + fb.y;
        if (is_goal) {
            g_pgh[(size_t)(row0 + i) * SDIM + lane]      = __float2half(va);
            g_pgh[(size_t)(row0 + i) * SDIM + lane + 32] = __float2half(vb);
        } else {
            g_buf1[(size_t)(row0 + i) * SDIM + lane]      = va;
            g_buf1[(size_t)(row0 + i) * SDIM + lane + 32] = vb;
        }
    }
}

// ---------------------------------------------------------------------------
// g1mlp1 (R10 structure + index software-pipelining): 256 threads, 32 rows.
//   gather: 8 thr/row, fp16 payload, next-group index load issued under
//           current group's value loads (breaks idx->value serial chain).
//   layer1: h = relu(h + b1) -> smem
//   layer2: x1 = relu(h @ W2 + b2) fp16-stored (f32x2 along K, warp = 4 rows)
#define HST 68
__global__ __launch_bounds__(256) void g1mlp1(const float* __restrict__ b1,
                                              const float* __restrict__ W2,
                                              const float* __restrict__ b2) {
    __shared__ float Hs[32 * HST];        // 8704 B
    __shared__ float W2t[SDIM * HST];     // 17408 B, W2t[c][k]
    int t = threadIdx.x;
    for (int i = t; i < SDIM * SDIM; i += 256) {
        int k = i >> 6, c = i & 63;
        W2t[c * HST + k] = W2[i];
    }

    // ---- gather: r = local row (32), q = 16B chunk (8) -> cols [8q,8q+8) ----
    int r = t >> 3, q = t & 7;
    int d = blockIdx.x * 32 + r;
    int n = g_cnt1[d]; if (n > CAP1) n = CAP1;
    const uint4* pgh = (const uint4*)g_pgh;   // 8 uint4 per row
    float a[8];
    {
        float4 s0 = ((const float4*)g_buf1)[d * 16 + 2 * q];
        float4 s1 = ((const float4*)g_buf1)[d * 16 + 2 * q + 1];
        a[0] = s0.x; a[1] = s0.y; a[2] = s0.z; a[3] = s0.w;
        a[4] = s1.x; a[5] = s1.y; a[6] = s1.z; a[7] = s1.w;
    }
    const int* bkt = g_bkt1 + d * CAP1;
    int j = 0;
    if (n >= 4) {
        int4 s4 = *(const int4*)(bkt);          // group 0 indices
        for (j = 0; j + 4 <= n; j += 4) {
            int4 nxt = s4;
            if (j + 8 <= n) nxt = *(const int4*)(bkt + j + 4);  // prefetch
            uint4 v0 = pgh[s4.x * 8 + q];
            uint4 v1 = pgh[s4.y * 8 + q];
            uint4 v2 = pgh[s4.z * 8 + q];
            uint4 v3 = pgh[s4.w * 8 + q];
            acc_h8(a, v0); acc_h8(a, v1); acc_h8(a, v2); acc_h8(a, v3);
            s4 = nxt;
        }
    }
    for (; j < n; j++) acc_h8(a, pgh[bkt[j] * 8 + q]);

#pragma unroll
    for (int i = 0; i < 8; i++) a[i] = fmaxf(a[i] + b1[8 * q + i], 0.f);
    *(float4*)&Hs[r * HST + 8 * q]     = make_float4(a[0], a[1], a[2], a[3]);
    *(float4*)&Hs[r * HST + 8 * q + 4] = make_float4(a[4], a[5], a[6], a[7]);
    __syncthreads();

    // ---- GEMM: warp owns 4 rows; lane owns cols {lane, lane+32} ----
    int warp = t >> 5, lane = t & 31;
    ull acc0[4] = {0ull, 0ull, 0ull, 0ull};
    ull acc1[4] = {0ull, 0ull, 0ull, 0ull};
    const float* hb = Hs + warp * 4 * HST;
#pragma unroll
    for (int k = 0; k < SDIM; k += 4) {
        ulonglong2 wA = *(const ulonglong2*)&W2t[lane * HST + k];
        ulonglong2 wB = *(const ulonglong2*)&W2t[(lane + 32) * HST + k];
#pragma unroll
        for (int i = 0; i < 4; i++) {
            ulonglong2 xh = *(const ulonglong2*)&hb[i * HST + k];
            acc0[i] = ffma2(xh.x, wA.x, acc0[i]);
            acc0[i] = ffma2(xh.y, wA.y, acc0[i]);
            acc1[i] = ffma2(xh.x, wB.x, acc1[i]);
            acc1[i] = ffma2(xh.y, wB.y, acc1[i]);
        }
    }
    int row0 = blockIdx.x * 32 + warp * 4;
    float b2a = b2[lane], b2b = b2[lane + 32];
#pragma unroll
    for (int i = 0; i < 4; i++) {
        float2 fa = unpack2(acc0[i]);
        float2 fb = unpack2(acc1[i]);
        g_x1h[(size_t)(row0 + i) * SDIM + lane] =
            __float2half(fmaxf(fa.x + fa.y + b2a, 0.f));
        g_x1h[(size_t)(row0 + i) * SDIM + lane + 32] =
            __float2half(fmaxf(fb.x + fb.y + b2b, 0.f));
    }
}

// ---------------------------------------------------------------------------
// gather2_split (R10 proven): edge-parallel agg2. Block = 8 rows x 32 thr.
__global__ __launch_bounds__(256) void gather2_split(const float4* __restrict__ x_task) {
    int t = threadIdx.x;
    int r = t >> 5;           // 0..7 (warp = one row)
    int h = (t >> 3) & 3;     // edge subset
    int q = t & 7;            // chunk
    int d = blockIdx.x * 8 + r;
    int n = g_cnt2[d]; if (n > CAP2) n = CAP2;
    const uint4* x1h = (const uint4*)g_x1h;
    float a[8];
#pragma unroll
    for (int i = 0; i < 8; i++) a[i] = 0.f;
    const int* bkt = g_bkt2 + d * CAP2;

    for (int j = h * 4; j + 4 <= n; j += 16) {
        int4 s4 = *(const int4*)(bkt + j);
        uint4 v0 = x1h[s4.x * 8 + q];
        uint4 v1 = x1h[s4.y * 8 + q];
        uint4 v2 = x1h[s4.z * 8 + q];
        uint4 v3 = x1h[s4.w * 8 + q];
        acc_h8(a, v0); acc_h8(a, v1); acc_h8(a, v2); acc_h8(a, v3);
    }
    if (h == ((n >> 2) & 3)) {           // remainder edges (n % 4)
        for (int jj = n & ~3; jj < n; jj++) acc_h8(a, x1h[bkt[jj] * 8 + q]);
    }
#pragma unroll
    for (int i = 0; i < 8; i++) {
        a[i] += __shfl_xor_sync(0xffffffffu, a[i], 8);
        a[i] += __shfl_xor_sync(0xffffffffu, a[i], 16);
    }
    if (h == 0) {
        float4 s0 = x_task[d * 16 + 2 * q];
        float4 s1 = x_task[d * 16 + 2 * q + 1];
        ((float4*)g_buf2)[d * 16 + 2 * q] =
            make_float4(a[0] + s0.x, a[1] + s0.y, a[2] + s0.z, a[3] + s0.w);
        ((float4*)g_buf2)[d * 16 + 2 * q + 1] =
            make_float4(a[4] + s1.x, a[5] + s1.y, a[6] + s1.z, a[7] + s1.w);
    }
}

// ---------------------------------------------------------------------------
// mlp2pool (R10 proven): block = one graph = 32 task rows, 256 threads.
#define XSTR 68
#define WSTR 65
__global__ __launch_bounds__(256) void mlp2pool(const float* __restrict__ W3,
                                                const float* __restrict__ b3,
                                                const float* __restrict__ W4,
                                                const float* __restrict__ b4,
                                                const float* __restrict__ Wc1,
                                                const float* __restrict__ bc1,
                                                const float* __restrict__ Wc2,
                                                const float* __restrict__ bc2,
                                                float* __restrict__ out) {
    __shared__ float Xs[32 * XSTR];
    __shared__ float W3t[SDIM * WSTR];    // transposed [c][k]
    __shared__ float W4s[SDIM], b3s[SDIM];
    __shared__ float scal[32];
    int t = threadIdx.x;
    for (int i = t; i < SDIM * SDIM; i += 256) {
        int k = i >> 6, c = i & 63;
        W3t[c * WSTR + k] = W3[i];
    }
    if (t < SDIM) { W4s[t] = W4[t]; b3s[t] = b3[t]; }

    int r = t >> 3, q = t & 7;
    int d = blockIdx.x * 32 + r;
    float4 a0 = ((const float4*)g_buf2)[d * 16 + 2 * q];
    float4 a1 = ((const float4*)g_buf2)[d * 16 + 2 * q + 1];
    *(float4*)&Xs[r * XSTR + 8 * q]     = a0;
    *(float4*)&Xs[r * XSTR + 8 * q + 4] = a1;
    __syncthreads();

    float s8[8];
    int cbase = q * 8;
#pragma unroll
    for (int i = 0; i < 8; i++) s8[i] = b3s[cbase + i];
    const float* xrow = Xs + r * XSTR;
#pragma unroll 4
    for (int k = 0; k < SDIM; k++) {
        float xv = xrow[k];
#pragma unroll
        for (int i = 0; i < 8; i++)
            s8[i] = fmaf(xv, W3t[(cbase + i) * WSTR + k], s8[i]);
    }
    float partial = 0.f;
#pragma unroll
    for (int i = 0; i < 8; i++)
        partial = fmaf(fmaxf(s8[i], 0.f), W4s[cbase + i], partial);
#pragma unroll
    for (int o = 1; o < 8; o <<= 1)
        partial += __shfl_xor_sync(0xffffffffu, partial, o);
    if (q == 0) scal[r] = partial + b4[0];
    __syncthreads();

    if (t < 32) {
        float v = scal[t];
        float vmax = v, vsum = v;
#pragma unroll
        for (int o = 16; o; o >>= 1) {
            vmax = fmaxf(vmax, __shfl_xor_sync(0xffffffffu, vmax, o));
            vsum += __shfl_xor_sync(0xffffffffu, vsum, o);
        }
        if (t == 0) {
            float mx = vmax;
            float mn = vsum * (1.f / 32.f);
            float rr = bc2[0];
#pragma unroll
            for (int i = 0; i < 8; i++) {
                float h = fmaxf(fmaf(mx, Wc1[i], fmaf(mn, Wc1[8 + i], bc1[i])), 0.f);
                rr = fmaf(h, Wc2[i], rr);
            }
            out[blockIdx.x] = rr;
        }
    }
}

// ---------------------------------------------------------------------------
extern "C" void kernel_launch(void* const* d_in, const int* in_sizes, int n_in,
                              void* d_out, int out_size) {
    const float* x_goal = (const float*)d_in[0];
    const float* x_obs  = (const float*)d_in[1];
    const float* x_task = (const float*)d_in[2];
    const int* ei_go_src = (const int*)d_in[3];
    const int* ei_go_dst = (const int*)d_in[4];
    const int* ei_ot_src = (const int*)d_in[5];
    const int* ei_ot_dst = (const int*)d_in[6];
    // d_in[7] = task_batch (contiguous; unused)
    const float* W1  = (const float*)d_in[8];
    const float* b1  = (const float*)d_in[9];
    const float* W2  = (const float*)d_in[10];
    const float* b2  = (const float*)d_in[11];
    const float* W3  = (const float*)d_in[12];
    const float* b3  = (const float*)d_in[13];
    const float* W4  = (const float*)d_in[14];
    const float* b4  = (const float*)d_in[15];
    const float* Wc1 = (const float*)d_in[16];
    const float* bc1 = (const float*)d_in[17];
    const float* Wc2 = (const float*)d_in[18];
    const float* bc2 = (const float*)d_in[19];
    float* out = (float*)d_out;

    void* cnt1p = nullptr; cudaGetSymbolAddress(&cnt1p, g_cnt1);
    void* cnt2p = nullptr; cudaGetSymbolAddress(&cnt2p, g_cnt2);

    const int PROJ_SMEM = 2 * 64 * XP * sizeof(float);   // 67584 B
    cudaFuncSetAttribute(projAll, cudaFuncAttributeMaxDynamicSharedMemorySize,
                         PROJ_SMEM);

    // 1. zero counters (async memset — graph-capturable, no alloc)
    cudaMemsetAsync(cnt1p, 0, N_OBS * sizeof(int), 0);
    cudaMemsetAsync(cnt2p, 0, N_TASK * sizeof(int), 0);
    // 2. bucket both edge sets
    build_all<<<(NE1 + NE2) / 256, 256>>>(ei_go_src, ei_go_dst, ei_ot_src, ei_ot_dst);
    // 3. pg(fp16) = x_goal @ W1 ; buf1(fp32) = x_obs @ W1
    projAll<<<(N_GOAL + N_OBS) / 64, 256, PROJ_SMEM>>>(x_goal, x_obs, W1);
    // 4. gather1(fp16 payload, idx-pipelined) + MLP1 fused -> x1 (fp16)
    g1mlp1<<<N_OBS / 32, 256>>>(b1, W2, b2);
    // 5. agg2 edge-parallel -> g_buf2 (fp32)
    gather2_split<<<N_TASK / 8, 256>>>((const float4*)x_task);
    // 6. MLP2 + pooling + critic -> out
    mlp2pool<<<N_TASK / 32, 256>>>(W3, b3, W4, b4, Wc1, bc1, Wc2, bc2, out);
}

// round 15
// speedup vs baseline: 1.1462x; 1.0920x over previous
#include <cuda_runtime.h>
#include <cuda_fp16.h>

#define N_GOAL 16384
#define N_OBS  65536
#define N_TASK 8192
#define NE1    1048576
#define NE2    1048576
#define FDIM   128
#define SDIM   64
#define CAP1   64
#define CAP2   256
#define NTILES ((N_GOAL + N_OBS) / 64)      // 1280 proj tiles
#define PROJ_GRID 444                        // 3 blocks/SM * 148 SMs (1 wave)

typedef unsigned long long ull;

// Scratch (static device globals — no runtime allocation)
__device__ __half g_pgh[N_GOAL * SDIM];  // x_goal @ W1 in fp16  (2 MB)
__device__ float  g_buf1[N_OBS * SDIM];  // x_obs  @ W1          (16 MB)
__device__ __half g_x1h[N_OBS * SDIM];   // x1 activations fp16  (8 MB)
__device__ float  g_buf2[N_TASK * SDIM]; // x_task + agg2        (2 MB)
__device__ int    g_cnt1[N_OBS];
__device__ int    g_cnt2[N_TASK];
__device__ int    g_bkt1[N_OBS * CAP1];  // (16 MB)
__device__ int    g_bkt2[N_TASK * CAP2]; // (8 MB)

// Packed f32x2 FMA (Blackwell): d = a*b + c lane-wise on two packed floats.
__device__ __forceinline__ ull ffma2(ull a, ull b, ull c) {
    ull d;
    asm("fma.rn.f32x2 %0, %1, %2, %3;" : "=l"(d) : "l"(a), "l"(b), "l"(c));
    return d;
}
__device__ __forceinline__ float2 unpack2(ull v) {
    float2 f;
    asm("mov.b64 {%0, %1}, %2;" : "=f"(f.x), "=f"(f.y) : "l"(v));
    return f;
}
// Accumulate 8 fp16 values (one uint4) into 8 fp32 accumulators.
__device__ __forceinline__ void acc_h8(float* a, uint4 v) {
    float2 f0 = __half22float2(*(const __half2*)&v.x);
    float2 f1 = __half22float2(*(const __half2*)&v.y);
    float2 f2 = __half22float2(*(const __half2*)&v.z);
    float2 f3 = __half22float2(*(const __half2*)&v.w);
    a[0] += f0.x; a[1] += f0.y; a[2] += f1.x; a[3] += f1.y;
    a[4] += f2.x; a[5] += f2.y; a[6] += f3.x; a[7] += f3.y;
}

// ---------------------------------------------------------------------------
// build_all: one pass over both edge sets; one 4B atomic per edge.
// Launched with PDL programmatic-serialization: runs CONCURRENTLY with the
// persistent projAll (no data dependency between them).
__global__ void build_all(const int* __restrict__ s1, const int* __restrict__ d1,
                          const int* __restrict__ s2, const int* __restrict__ d2) {
    int e = blockIdx.x * blockDim.x + threadIdx.x;
    if (e < NE1) {
        int s = s1[e], d = d1[e];
        int slot = atomicAdd(&g_cnt1[d], 1);
        if (slot < CAP1) g_bkt1[d * CAP1 + slot] = s;
    } else {
        int e2 = e - NE1;
        int s = s2[e2], d = d2[e2];
        int slot = atomicAdd(&g_cnt2[d], 1);
        if (slot < CAP2) g_bkt2[d * CAP2 + slot] = s;
    }
}

// ---------------------------------------------------------------------------
// projAll (persistent): grid = PROJ_GRID blocks, each loops over tiles.
// All blocks resident in wave 1 -> cudaTriggerProgrammaticLaunchCompletion at
// block start fires the PDL trigger immediately, releasing build_all.
// Tiles 0..N_GOAL/64-1 -> g_pgh (fp16); rest -> g_buf1 (fp32).
#define XP 132
__global__ __launch_bounds__(256) void projAll(const float* __restrict__ xg,
                                               const float* __restrict__ xo,
                                               const float* __restrict__ W) {
    cudaTriggerProgrammaticLaunchCompletion();

    extern __shared__ float sm[];
    float* Xs = sm;                 // 64 rows x XP   (33792 B)
    float* Wt = sm + 64 * XP;       // Wt[c][k], 64 x XP (33792 B)
    int t = threadIdx.x;
    int warp = t >> 5, lane = t & 31;

    // Stage W once per block (covered by the first in-loop __syncthreads).
    for (int i = t; i < FDIM * SDIM; i += 256) {
        int k = i >> 6, c = i & 63;
        Wt[c * XP + k] = W[i];
    }

    for (int tile = blockIdx.x; tile < NTILES; tile += PROJ_GRID) {
        const float* X; int rowbase; bool is_goal;
        if (tile < N_GOAL / 64) {
            X = xg; rowbase = tile * 64; is_goal = true;
        } else {
            X = xo; rowbase = (tile - N_GOAL / 64) * 64; is_goal = false;
        }

        __syncthreads();   // prev iter's Xs reads done (also orders W staging)
        const float4* X4 = (const float4*)(X + (size_t)rowbase * FDIM);
        for (int i = t; i < 64 * 32; i += 256) {
            int row = i >> 5, kq = i & 31;
            *(float4*)&Xs[row * XP + kq * 4] = X4[row * 32 + kq];
        }
        __syncthreads();

        ull acc0[8], acc1[8];
#pragma unroll
        for (int i = 0; i < 8; i++) { acc0[i] = 0ull; acc1[i] = 0ull; }

        const float* xb = Xs + warp * 8 * XP;
#pragma unroll 4
        for (int k = 0; k < FDIM; k += 4) {
            ulonglong2 wA = *(const ulonglong2*)&Wt[lane * XP + k];
            ulonglong2 wB = *(const ulonglong2*)&Wt[(lane + 32) * XP + k];
#pragma unroll
            for (int i = 0; i < 8; i++) {
                ulonglong2 xh = *(const ulonglong2*)&xb[i * XP + k];
                acc0[i] = ffma2(xh.x, wA.x, acc0[i]);
                acc0[i] = ffma2(xh.y, wA.y, acc0[i]);
                acc1[i] = ffma2(xh.x, wB.x, acc1[i]);
                acc1[i] = ffma2(xh.y, wB.y, acc1[i]);
            }
        }
        int row0 = rowbase + warp * 8;
#pragma unroll
        for (int i = 0; i < 8; i++) {
            float2 fa = unpack2(acc0[i]);
            float2 fb = unpack2(acc1[i]);
            float va = fa.x + fa.y, vb = fb.x + fb.y;
            if (is_goal) {
                g_pgh[(size_t)(row0 + i) * SDIM + lane]      = __float2half(va);
                g_pgh[(size_t)(row0 + i) * SDIM + lane + 32] = __float2half(vb);
            } else {
                g_buf1[(size_t)(row0 + i) * SDIM + lane]      = va;
                g_buf1[(size_t)(row0 + i) * SDIM + lane + 32] = vb;
            }
        }
    }
}

// ---------------------------------------------------------------------------
// g1mlp1 (R13): 256 threads, 32 obs rows/block.
#define HST 68
__global__ __launch_bounds__(256) void g1mlp1(const float* __restrict__ b1,
                                              const float* __restrict__ W2,
                                              const float* __restrict__ b2) {
    __shared__ float Hs[32 * HST];        // 8704 B
    __shared__ float W2t[SDIM * HST];     // 17408 B, W2t[c][k]
    int t = threadIdx.x;
    for (int i = t; i < SDIM * SDIM; i += 256) {
        int k = i >> 6, c = i & 63;
        W2t[c * HST + k] = W2[i];
    }

    // ---- gather: r = local row (32), q = 16B chunk (8) -> cols [8q,8q+8) ----
    int r = t >> 3, q = t & 7;
    int d = blockIdx.x * 32 + r;
    int n = g_cnt1[d]; if (n > CAP1) n = CAP1;
    const uint4* pgh = (const uint4*)g_pgh;   // 8 uint4 per row
    float a[8];
    {
        float4 s0 = ((const float4*)g_buf1)[d * 16 + 2 * q];
        float4 s1 = ((const float4*)g_buf1)[d * 16 + 2 * q + 1];
        a[0] = s0.x; a[1] = s0.y; a[2] = s0.z; a[3] = s0.w;
        a[4] = s1.x; a[5] = s1.y; a[6] = s1.z; a[7] = s1.w;
    }
    const int* bkt = g_bkt1 + d * CAP1;
    int j = 0;
    if (n >= 4) {
        int4 s4 = *(const int4*)(bkt);          // group 0 indices
        for (j = 0; j + 4 <= n; j += 4) {
            int4 nxt = s4;
            if (j + 8 <= n) nxt = *(const int4*)(bkt + j + 4);  // prefetch
            uint4 v0 = pgh[s4.x * 8 + q];
            uint4 v1 = pgh[s4.y * 8 + q];
            uint4 v2 = pgh[s4.z * 8 + q];
            uint4 v3 = pgh[s4.w * 8 + q];
            acc_h8(a, v0); acc_h8(a, v1); acc_h8(a, v2); acc_h8(a, v3);
            s4 = nxt;
        }
    }
    for (; j < n; j++) acc_h8(a, pgh[bkt[j] * 8 + q]);

#pragma unroll
    for (int i = 0; i < 8; i++) a[i] = fmaxf(a[i] + b1[8 * q + i], 0.f);
    *(float4*)&Hs[r * HST + 8 * q]     = make_float4(a[0], a[1], a[2], a[3]);
    *(float4*)&Hs[r * HST + 8 * q + 4] = make_float4(a[4], a[5], a[6], a[7]);
    __syncthreads();

    // ---- GEMM: warp owns 4 rows; lane owns cols {lane, lane+32} ----
    int warp = t >> 5, lane = t & 31;
    ull acc0[4] = {0ull, 0ull, 0ull, 0ull};
    ull acc1[4] = {0ull, 0ull, 0ull, 0ull};
    const float* hb = Hs + warp * 4 * HST;
#pragma unroll
    for (int k = 0; k < SDIM; k += 4) {
        ulonglong2 wA = *(const ulonglong2*)&W2t[lane * HST + k];
        ulonglong2 wB = *(const ulonglong2*)&W2t[(lane + 32) * HST + k];
#pragma unroll
        for (int i = 0; i < 4; i++) {
            ulonglong2 xh = *(const ulonglong2*)&hb[i * HST + k];
            acc0[i] = ffma2(xh.x, wA.x, acc0[i]);
            acc0[i] = ffma2(xh.y, wA.y, acc0[i]);
            acc1[i] = ffma2(xh.x, wB.x, acc1[i]);
            acc1[i] = ffma2(xh.y, wB.y, acc1[i]);
        }
    }
    int row0 = blockIdx.x * 32 + warp * 4;
    float b2a = b2[lane], b2b = b2[lane + 32];
#pragma unroll
    for (int i = 0; i < 4; i++) {
        float2 fa = unpack2(acc0[i]);
        float2 fb = unpack2(acc1[i]);
        g_x1h[(size_t)(row0 + i) * SDIM + lane] =
            __float2half(fmaxf(fa.x + fa.y + b2a, 0.f));
        g_x1h[(size_t)(row0 + i) * SDIM + lane + 32] =
            __float2half(fmaxf(fb.x + fb.y + b2b, 0.f));
    }
}

// ---------------------------------------------------------------------------
// gather2_split (proven): edge-parallel agg2. Block = 8 rows x 32 thr.
__global__ __launch_bounds__(256) void gather2_split(const float4* __restrict__ x_task) {
    int t = threadIdx.x;
    int r = t >> 5;           // 0..7 (warp = one row)
    int h = (t >> 3) & 3;     // edge subset
    int q = t & 7;            // chunk
    int d = blockIdx.x * 8 + r;
    int n = g_cnt2[d]; if (n > CAP2) n = CAP2;
    const uint4* x1h = (const uint4*)g_x1h;
    float a[8];
#pragma unroll
    for (int i = 0; i < 8; i++) a[i] = 0.f;
    const int* bkt = g_bkt2 + d * CAP2;

    for (int j = h * 4; j + 4 <= n; j += 16) {
        int4 s4 = *(const int4*)(bkt + j);
        uint4 v0 = x1h[s4.x * 8 + q];
        uint4 v1 = x1h[s4.y * 8 + q];
        uint4 v2 = x1h[s4.z * 8 + q];
        uint4 v3 = x1h[s4.w * 8 + q];
        acc_h8(a, v0); acc_h8(a, v1); acc_h8(a, v2); acc_h8(a, v3);
    }
    if (h == ((n >> 2) & 3)) {           // remainder edges (n % 4)
        for (int jj = n & ~3; jj < n; jj++) acc_h8(a, x1h[bkt[jj] * 8 + q]);
    }
#pragma unroll
    for (int i = 0; i < 8; i++) {
        a[i] += __shfl_xor_sync(0xffffffffu, a[i], 8);
        a[i] += __shfl_xor_sync(0xffffffffu, a[i], 16);
    }
    if (h == 0) {
        float4 s0 = x_task[d * 16 + 2 * q];
        float4 s1 = x_task[d * 16 + 2 * q + 1];
        ((float4*)g_buf2)[d * 16 + 2 * q] =
            make_float4(a[0] + s0.x, a[1] + s0.y, a[2] + s0.z, a[3] + s0.w);
        ((float4*)g_buf2)[d * 16 + 2 * q + 1] =
            make_float4(a[4] + s1.x, a[5] + s1.y, a[6] + s1.z, a[7] + s1.w);
    }
}

// ---------------------------------------------------------------------------
// mlp2pool (proven): block = one graph = 32 task rows, 256 threads.
#define XSTR 68
#define WSTR 65
__global__ __launch_bounds__(256) void mlp2pool(const float* __restrict__ W3,
                                                const float* __restrict__ b3,
                                                const float* __restrict__ W4,
                                                const float* __restrict__ b4,
                                                const float* __restrict__ Wc1,
                                                const float* __restrict__ bc1,
                                                const float* __restrict__ Wc2,
                                                const float* __restrict__ bc2,
                                                float* __restrict__ out) {
    __shared__ float Xs[32 * XSTR];
    __shared__ float W3t[SDIM * WSTR];    // transposed [c][k]
    __shared__ float W4s[SDIM], b3s[SDIM];
    __shared__ float scal[32];
    int t = threadIdx.x;
    for (int i = t; i < SDIM * SDIM; i += 256) {
        int k = i >> 6, c = i & 63;
        W3t[c * WSTR + k] = W3[i];
    }
    if (t < SDIM) { W4s[t] = W4[t]; b3s[t] = b3[t]; }

    int r = t >> 3, q = t & 7;
    int d = blockIdx.x * 32 + r;
    float4 a0 = ((const float4*)g_buf2)[d * 16 + 2 * q];
    float4 a1 = ((const float4*)g_buf2)[d * 16 + 2 * q + 1];
    *(float4*)&Xs[r * XSTR + 8 * q]     = a0;
    *(float4*)&Xs[r * XSTR + 8 * q + 4] = a1;
    __syncthreads();

    float s8[8];
    int cbase = q * 8;
#pragma unroll
    for (int i = 0; i < 8; i++) s8[i] = b3s[cbase + i];
    const float* xrow = Xs + r * XSTR;
#pragma unroll 4
    for (int k = 0; k < SDIM; k++) {
        float xv = xrow[k];
#pragma unroll
        for (int i = 0; i < 8; i++)
            s8[i] = fmaf(xv, W3t[(cbase + i) * WSTR + k], s8[i]);
    }
    float partial = 0.f;
#pragma unroll
    for (int i = 0; i < 8; i++)
        partial = fmaf(fmaxf(s8[i], 0.f), W4s[cbase + i], partial);
#pragma unroll
    for (int o = 1; o < 8; o <<= 1)
        partial += __shfl_xor_sync(0xffffffffu, partial, o);
    if (q == 0) scal[r] = partial + b4[0];
    __syncthreads();

    if (t < 32) {
        float v = scal[t];
        float vmax = v, vsum = v;
#pragma unroll
        for (int o = 16; o; o >>= 1) {
            vmax = fmaxf(vmax, __shfl_xor_sync(0xffffffffu, vmax, o));
            vsum += __shfl_xor_sync(0xffffffffu, vsum, o);
        }
        if (t == 0) {
            float mx = vmax;
            float mn = vsum * (1.f / 32.f);
            float rr = bc2[0];
#pragma unroll
            for (int i = 0; i < 8; i++) {
                float h = fmaxf(fmaf(mx, Wc1[i], fmaf(mn, Wc1[8 + i], bc1[i])), 0.f);
                rr = fmaf(h, Wc2[i], rr);
            }
            out[blockIdx.x] = rr;
        }
    }
}

// ---------------------------------------------------------------------------
extern "C" void kernel_launch(void* const* d_in, const int* in_sizes, int n_in,
                              void* d_out, int out_size) {
    const float* x_goal = (const float*)d_in[0];
    const float* x_obs  = (const float*)d_in[1];
    const float* x_task = (const float*)d_in[2];
    const int* ei_go_src = (const int*)d_in[3];
    const int* ei_go_dst = (const int*)d_in[4];
    const int* ei_ot_src = (const int*)d_in[5];
    const int* ei_ot_dst = (const int*)d_in[6];
    // d_in[7] = task_batch (contiguous; unused)
    const float* W1  = (const float*)d_in[8];
    const float* b1  = (const float*)d_in[9];
    const float* W2  = (const float*)d_in[10];
    const float* b2  = (const float*)d_in[11];
    const float* W3  = (const float*)d_in[12];
    const float* b3  = (const float*)d_in[13];
    const float* W4  = (const float*)d_in[14];
    const float* b4  = (const float*)d_in[15];
    const float* Wc1 = (const float*)d_in[16];
    const float* bc1 = (const float*)d_in[17];
    const float* Wc2 = (const float*)d_in[18];
    const float* bc2 = (const float*)d_in[19];
    float* out = (float*)d_out;

    void* cnt1p = nullptr; cudaGetSymbolAddress(&cnt1p, g_cnt1);
    void* cnt2p = nullptr; cudaGetSymbolAddress(&cnt2p, g_cnt2);

    const int PROJ_SMEM = 2 * 64 * XP * sizeof(float);   // 67584 B
    cudaFuncSetAttribute(projAll, cudaFuncAttributeMaxDynamicSharedMemorySize,
                         PROJ_SMEM);

    // 1. zero counters (async memset — graph-capturable, no alloc)
    cudaMemsetAsync(cnt1p, 0, N_OBS * sizeof(int), 0);
    cudaMemsetAsync(cnt2p, 0, N_TASK * sizeof(int), 0);

    // 2. persistent projection GEMM: all blocks resident in wave 1, trigger
    //    PDL completion immediately.
    projAll<<<PROJ_GRID, 256, PROJ_SMEM>>>(x_goal, x_obs, W1);

    // 3. bucket build, PDL-overlapped with projAll (no data dependency).
    {
        cudaLaunchConfig_t cfg = {};
        cfg.gridDim = dim3((NE1 + NE2) / 256, 1, 1);
        cfg.blockDim = dim3(256, 1, 1);
        cfg.dynamicSmemBytes = 0;
        cfg.stream = 0;
        cudaLaunchAttribute attr[1];
        attr[0].id = cudaLaunchAttributeProgrammaticStreamSerialization;
        attr[0].val.programmaticStreamSerializationAllowed = 1;
        cfg.attrs = attr;
        cfg.numAttrs = 1;
        cudaLaunchKernelEx(&cfg, build_all,
                           ei_go_src, ei_go_dst, ei_ot_src, ei_ot_dst);
    }

    // 4. gather1 + MLP1 fused -> x1 (waits on BOTH projAll and build_all)
    g1mlp1<<<N_OBS / 32, 256>>>(b1, W2, b2);
    // 5. agg2 edge-parallel -> g_buf2 (fp32)
    gather2_split<<<N_TASK / 8, 256>>>((const float4*)x_task);
    // 6. MLP2 + pooling + critic -> out
    mlp2pool<<<N_TASK / 32, 256>>>(W3, b3, W4, b4, Wc1, bc1, Wc2, bc2, out);
}